// round 3
// baseline (speedup 1.0000x reference)
#include <cuda_runtime.h>
#include <cuda_bf16.h>

#define N_NODES 100000
#define N_EDGES 1600000
#define IN_CH   128
#define NG      16

#define SCAN_BLK   1024
#define SCAN_NB    ((N_NODES + SCAN_BLK - 1) / SCAN_BLK)   // 98

// ---------------- scratch (device globals) ----------------------------------
__device__ float g_y  [N_NODES * 64];     // x @ W_l^T
__device__ float g_xr [N_NODES * 64];     // x @ W_r^T
__device__ int   g_cnt   [N_NODES];       // in-degree histogram
__device__ int   g_rowptr[N_NODES + 1];   // CSR row pointers (by dst)
__device__ int   g_pos   [N_NODES];       // fill cursors
__device__ int   g_blocksum[SCAN_NB];
__device__ int   g_blockoff[SCAN_NB];
__device__ int   g_elist [N_EDGES];       // src per slot
__device__ float g_gsum[NG * 64];
__device__ float g_gcnt[NG];

// ---------------- kernel 1: zero small scratch -------------------------------
__global__ void zero_kernel() {
    int i = blockIdx.x * blockDim.x + threadIdx.x;
    int stride = gridDim.x * blockDim.x;
    for (int j = i; j < N_NODES; j += stride) g_cnt[j] = 0;
    for (int j = i; j < NG * 64; j += stride) g_gsum[j] = 0.f;
    for (int j = i; j < NG; j += stride) g_gcnt[j] = 0.f;
    if (i == 0) g_rowptr[N_NODES] = N_EDGES;
}

// ---------------- kernel 2: fused node GEMM ----------------------------------
#define GEMM_BM 64
__global__ void node_gemm(const float* __restrict__ x,
                          const float* __restrict__ Wl,
                          const float* __restrict__ Wr) {
    extern __shared__ float smem[];
    float* Ws = smem;              // [128][128]  Ws[k][j] = Wcat[j][k]
    float* Xs = smem + 128 * 128;  // [64][132]

    int tid = threadIdx.x;
    for (int idx = tid; idx < 128 * 128; idx += 256) {
        int j = idx >> 7, k = idx & 127;
        float v = (j < 64) ? Wl[j * 128 + k] : Wr[(j - 64) * 128 + k];
        Ws[k * 128 + j] = v;
    }
    int nodeBase = blockIdx.x * GEMM_BM;
    for (int idx = tid; idx < GEMM_BM * 128; idx += 256) {
        int r = idx >> 7, k = idx & 127;
        int n = nodeBase + r;
        Xs[r * 132 + k] = (n < N_NODES) ? x[(size_t)n * 128 + k] : 0.f;
    }
    __syncthreads();

    int ty = tid >> 4, tx = tid & 15;
    float acc[4][8];
#pragma unroll
    for (int r = 0; r < 4; r++)
#pragma unroll
        for (int c = 0; c < 8; c++) acc[r][c] = 0.f;

#pragma unroll 4
    for (int k = 0; k < 128; k++) {
        float xv[4];
#pragma unroll
        for (int r = 0; r < 4; r++) xv[r] = Xs[(ty * 4 + r) * 132 + k];
        float4 w0 = *reinterpret_cast<const float4*>(&Ws[k * 128 + tx * 8]);
        float4 w1 = *reinterpret_cast<const float4*>(&Ws[k * 128 + tx * 8 + 4]);
        float wv[8] = {w0.x, w0.y, w0.z, w0.w, w1.x, w1.y, w1.z, w1.w};
#pragma unroll
        for (int r = 0; r < 4; r++)
#pragma unroll
            for (int c = 0; c < 8; c++) acc[r][c] = fmaf(xv[r], wv[c], acc[r][c]);
    }

    int j = tx * 8;
#pragma unroll
    for (int r = 0; r < 4; r++) {
        int n = nodeBase + ty * 4 + r;
        if (n >= N_NODES) continue;
        float4 o0 = make_float4(acc[r][0], acc[r][1], acc[r][2], acc[r][3]);
        float4 o1 = make_float4(acc[r][4], acc[r][5], acc[r][6], acc[r][7]);
        if (j < 64) {
            *reinterpret_cast<float4*>(&g_y[(size_t)n * 64 + j])     = o0;
            *reinterpret_cast<float4*>(&g_y[(size_t)n * 64 + j + 4]) = o1;
        } else {
            *reinterpret_cast<float4*>(&g_xr[(size_t)n * 64 + j - 64])     = o0;
            *reinterpret_cast<float4*>(&g_xr[(size_t)n * 64 + j - 64 + 4]) = o1;
        }
    }
}

// ---------------- kernel 3: degree histogram ---------------------------------
__global__ void hist_kernel(const int* __restrict__ ei) {
    int e = blockIdx.x * blockDim.x + threadIdx.x;
    if (e >= N_EDGES) return;
    int dst = __ldg(&ei[N_EDGES + e]);
    asm volatile("red.global.add.s32 [%0], %1;" :: "l"(g_cnt + dst), "r"(1) : "memory");
}

// ---------------- kernels 4-6: exclusive prefix scan -------------------------
__global__ void scan1_kernel() {
    __shared__ int warp_sums[32];
    int gid = blockIdx.x * SCAN_BLK + threadIdx.x;
    int lane = threadIdx.x & 31, wid = threadIdx.x >> 5;
    int v = (gid < N_NODES) ? g_cnt[gid] : 0;
    int s = v;
#pragma unroll
    for (int o = 1; o < 32; o <<= 1) {
        int t = __shfl_up_sync(0xffffffffu, s, o);
        if (lane >= o) s += t;
    }
    if (lane == 31) warp_sums[wid] = s;
    __syncthreads();
    if (wid == 0) {
        int t = warp_sums[lane];
        int si = t;
#pragma unroll
        for (int o = 1; o < 32; o <<= 1) {
            int u = __shfl_up_sync(0xffffffffu, si, o);
            if (lane >= o) si += u;
        }
        warp_sums[lane] = si - t;  // exclusive
    }
    __syncthreads();
    int excl = s - v + warp_sums[wid];
    if (gid < N_NODES) g_rowptr[gid] = excl;
    if (threadIdx.x == SCAN_BLK - 1) g_blocksum[blockIdx.x] = excl + v;
}

__global__ void scan2_kernel() {
    __shared__ int warp_sums[4];
    int tid = threadIdx.x;                      // 128 threads
    int lane = tid & 31, wid = tid >> 5;
    int v = (tid < SCAN_NB) ? g_blocksum[tid] : 0;
    int s = v;
#pragma unroll
    for (int o = 1; o < 32; o <<= 1) {
        int t = __shfl_up_sync(0xffffffffu, s, o);
        if (lane >= o) s += t;
    }
    if (lane == 31) warp_sums[wid] = s;
    __syncthreads();
    int woff = 0;
    for (int w = 0; w < wid; w++) woff += warp_sums[w];
    if (tid < SCAN_NB) g_blockoff[tid] = s - v + woff;
}

__global__ void scan3_kernel() {
    int gid = blockIdx.x * SCAN_BLK + threadIdx.x;
    if (gid >= N_NODES) return;
    int rp = g_rowptr[gid] + g_blockoff[blockIdx.x];
    g_rowptr[gid] = rp;
    g_pos[gid] = rp;
}

// ---------------- kernel 7: CSR fill -----------------------------------------
__global__ void fill_kernel(const int* __restrict__ ei) {
    int e = blockIdx.x * blockDim.x + threadIdx.x;
    if (e >= N_EDGES) return;
    int src = __ldg(&ei[e]);
    int dst = __ldg(&ei[N_EDGES + e]);
    int pos = atomicAdd(&g_pos[dst], 1);
    g_elist[pos] = src;
}

// ---------------- kernel 8: fused pull + combine + per-graph pool ------------
#define PULL_BLOCKS 256
#define PULL_WARPS  (PULL_BLOCKS * 8)
#define PULL_CHUNK  ((N_NODES + PULL_WARPS - 1) / PULL_WARPS)
__global__ void pull_pool(const float* __restrict__ bl,
                          const int* __restrict__ batch) {
    int wid = (blockIdx.x * blockDim.x + threadIdx.x) >> 5;
    int lane = threadIdx.x & 31;
    int start = wid * PULL_CHUNK;
    if (start >= N_NODES) return;
    int end = min(start + PULL_CHUNK, N_NODES);

    float bl0 = bl[lane], bl1 = bl[lane + 32];
    float acc0 = 0.f, acc1 = 0.f, cnt = 0.f;
    int cur = batch[start];

    int re = g_rowptr[start];
    for (int n = start; n < end; n++) {
        int b = batch[n];
        if (b != cur) {
            atomicAdd(&g_gsum[cur * 64 + lane], acc0);
            atomicAdd(&g_gsum[cur * 64 + lane + 32], acc1);
            if (lane == 0) atomicAdd(&g_gcnt[cur], cnt);
            acc0 = acc1 = cnt = 0.f;
            cur = b;
        }
        int rs = re;
        re = g_rowptr[n + 1];
        int deg = re - rs;

        float a0 = 0.f, a1 = 0.f;
        for (int base = rs; base < re; base += 32) {
            int m = min(32, re - base);
            int sv = (lane < m) ? g_elist[base + lane] : 0;
#pragma unroll 4
            for (int k = 0; k < m; k++) {
                int s = __shfl_sync(0xffffffffu, sv, k);
                size_t yb = (size_t)s * 64;
                a0 += g_y[yb + lane];
                a1 += g_y[yb + lane + 32];
            }
        }
        float inv = 1.0f / fmaxf((float)deg, 1.0f);
        size_t xb = (size_t)n * 64;
        float h0 = fmaxf(fmaf(a0, inv, g_xr[xb + lane]      + bl0), 0.f);
        float h1 = fmaxf(fmaf(a1, inv, g_xr[xb + lane + 32] + bl1), 0.f);
        acc0 += h0; acc1 += h1; cnt += 1.f;
    }
    atomicAdd(&g_gsum[cur * 64 + lane], acc0);
    atomicAdd(&g_gsum[cur * 64 + lane + 32], acc1);
    if (lane == 0) atomicAdd(&g_gcnt[cur], cnt);
}

// ---------------- kernel 9: final MLP (16 graphs, 1 block) -------------------
__global__ void final_mlp(const float* __restrict__ pk, const float* __restrict__ ck,
                          const float* __restrict__ Wp, const float* __restrict__ bp,
                          const float* __restrict__ Wc, const float* __restrict__ bc,
                          const float* __restrict__ Wh1, const float* __restrict__ bh1,
                          const float* __restrict__ Wh2, const float* __restrict__ bh2,
                          float* __restrict__ out) {
    __shared__ float z[NG][128];
    int w = threadIdx.x >> 5;
    int lane = threadIdx.x & 31;

    float cnt = fmaxf(g_gcnt[w], 1.0f);
    z[w][lane]      = g_gsum[w * 64 + lane] / cnt;
    z[w][lane + 32] = g_gsum[w * 64 + lane + 32] / cnt;

    float s = bp[lane];
#pragma unroll
    for (int k = 0; k < 7; k++) s = fmaf(pk[w * 7 + k], Wp[lane * 7 + k], s);
    z[w][64 + lane] = fmaxf(s, 0.f);

    s = bc[lane];
#pragma unroll
    for (int k = 0; k < 4; k++) s = fmaf(ck[w * 4 + k], Wc[lane * 4 + k], s);
    z[w][96 + lane] = fmaxf(s, 0.f);
    __syncwarp();

    float a0 = bh1[lane], a1 = bh1[lane + 32];
#pragma unroll 4
    for (int k = 0; k < 128; k++) {
        float zv = z[w][k];
        a0 = fmaf(zv, Wh1[lane * 128 + k], a0);
        a1 = fmaf(zv, Wh1[(lane + 32) * 128 + k], a1);
    }
    a0 = fmaxf(a0, 0.f);
    a1 = fmaxf(a1, 0.f);
    float r = a0 * Wh2[lane] + a1 * Wh2[lane + 32];
#pragma unroll
    for (int off = 16; off > 0; off >>= 1) r += __shfl_down_sync(0xffffffffu, r, off);
    if (lane == 0) out[w] = r + bh2[0];
}

// ---------------- launch -----------------------------------------------------
extern "C" void kernel_launch(void* const* d_in, const int* in_sizes, int n_in,
                              void* d_out, int out_size) {
    const float* x    = (const float*)d_in[0];
    const float* pk   = (const float*)d_in[1];
    const float* ck   = (const float*)d_in[2];
    const float* Wl   = (const float*)d_in[3];
    const float* bl   = (const float*)d_in[4];
    const float* Wr   = (const float*)d_in[5];
    const float* Wp   = (const float*)d_in[6];
    const float* bp   = (const float*)d_in[7];
    const float* Wc   = (const float*)d_in[8];
    const float* bc   = (const float*)d_in[9];
    const float* Wh1  = (const float*)d_in[10];
    const float* bh1  = (const float*)d_in[11];
    const float* Wh2  = (const float*)d_in[12];
    const float* bh2  = (const float*)d_in[13];
    const int*   ei   = (const int*)d_in[14];
    const int*   batch= (const int*)d_in[15];
    float* out = (float*)d_out;

    zero_kernel<<<256, 256>>>();

    int gemm_smem = (128 * 128 + GEMM_BM * 132) * (int)sizeof(float);
    cudaFuncSetAttribute(node_gemm, cudaFuncAttributeMaxDynamicSharedMemorySize, gemm_smem);
    node_gemm<<<(N_NODES + GEMM_BM - 1) / GEMM_BM, 256, gemm_smem>>>(x, Wl, Wr);

    hist_kernel<<<(N_EDGES + 255) / 256, 256>>>(ei);
    scan1_kernel<<<SCAN_NB, SCAN_BLK>>>();
    scan2_kernel<<<1, 128>>>();
    scan3_kernel<<<SCAN_NB, SCAN_BLK>>>();
    fill_kernel<<<(N_EDGES + 255) / 256, 256>>>(ei);

    pull_pool<<<PULL_BLOCKS, 256>>>(bl, batch);

    final_mlp<<<1, 512>>>(pk, ck, Wp, bp, Wc, bc, Wh1, bh1, Wh2, bh2, out);

    (void)in_sizes; (void)n_in; (void)out_size;
}

// round 4
// speedup vs baseline: 1.2876x; 1.2876x over previous
#include <cuda_runtime.h>
#include <cuda_bf16.h>

#define N_NODES 100000
#define N_EDGES 1600000
#define IN_CH   128
#define NG      16

// ---------------- scratch (device globals) ----------------------------------
__device__ float g_y  [N_NODES * 64];   // x @ W_l^T
__device__ float g_xr [N_NODES * 64];   // x @ W_r^T
__device__ float g_agg[N_NODES * 64];   // segment_sum of y over dst
__device__ float g_deg[N_NODES];
__device__ float g_gsum[NG * 64];
__device__ float g_gcnt[NG];

// ---------------- kernel 1: zero agg + deg ----------------------------------
__global__ void zero_agg() {
    int i = blockIdx.x * blockDim.x + threadIdx.x;
    int stride = gridDim.x * blockDim.x;
    float4 z4 = make_float4(0.f, 0.f, 0.f, 0.f);
    float4* a4 = reinterpret_cast<float4*>(g_agg);
    for (int j = i; j < N_NODES * 16; j += stride) a4[j] = z4;
    for (int j = i; j < N_NODES; j += stride) g_deg[j] = 0.f;
}

// ---------------- kernel 3 (slot 3): zero pool accumulators ------------------
__global__ void zero_small() {
    int i = threadIdx.x;
    if (i < NG * 64) g_gsum[i] = 0.f;
    if (i < NG) g_gcnt[i] = 0.f;
}

// ---------------- kernel 2: fused node GEMM ----------------------------------
// [y | xr] = x @ [W_l ; W_r]^T. 64 nodes x 128 outs / block, 256 thr, 4x8.
#define GEMM_BM 64
__global__ void node_gemm(const float* __restrict__ x,
                          const float* __restrict__ Wl,
                          const float* __restrict__ Wr) {
    extern __shared__ float smem[];
    float* Ws = smem;              // [128][128]  Ws[k][j] = Wcat[j][k]
    float* Xs = smem + 128 * 128;  // [64][132]

    int tid = threadIdx.x;
    for (int idx = tid; idx < 128 * 128; idx += 256) {
        int j = idx >> 7, k = idx & 127;
        float v = (j < 64) ? Wl[j * 128 + k] : Wr[(j - 64) * 128 + k];
        Ws[k * 128 + j] = v;
    }
    int nodeBase = blockIdx.x * GEMM_BM;
    for (int idx = tid; idx < GEMM_BM * 128; idx += 256) {
        int r = idx >> 7, k = idx & 127;
        int n = nodeBase + r;
        Xs[r * 132 + k] = (n < N_NODES) ? x[(size_t)n * 128 + k] : 0.f;
    }
    __syncthreads();

    int ty = tid >> 4, tx = tid & 15;
    float acc[4][8];
#pragma unroll
    for (int r = 0; r < 4; r++)
#pragma unroll
        for (int c = 0; c < 8; c++) acc[r][c] = 0.f;

#pragma unroll 4
    for (int k = 0; k < 128; k++) {
        float xv[4];
#pragma unroll
        for (int r = 0; r < 4; r++) xv[r] = Xs[(ty * 4 + r) * 132 + k];
        float4 w0 = *reinterpret_cast<const float4*>(&Ws[k * 128 + tx * 8]);
        float4 w1 = *reinterpret_cast<const float4*>(&Ws[k * 128 + tx * 8 + 4]);
        float wv[8] = {w0.x, w0.y, w0.z, w0.w, w1.x, w1.y, w1.z, w1.w};
#pragma unroll
        for (int r = 0; r < 4; r++)
#pragma unroll
            for (int c = 0; c < 8; c++) acc[r][c] = fmaf(xv[r], wv[c], acc[r][c]);
    }

    int j = tx * 8;
#pragma unroll
    for (int r = 0; r < 4; r++) {
        int n = nodeBase + ty * 4 + r;
        if (n >= N_NODES) continue;
        float4 o0 = make_float4(acc[r][0], acc[r][1], acc[r][2], acc[r][3]);
        float4 o1 = make_float4(acc[r][4], acc[r][5], acc[r][6], acc[r][7]);
        if (j < 64) {
            *reinterpret_cast<float4*>(&g_y[(size_t)n * 64 + j])     = o0;
            *reinterpret_cast<float4*>(&g_y[(size_t)n * 64 + j + 4]) = o1;
        } else {
            *reinterpret_cast<float4*>(&g_xr[(size_t)n * 64 + j - 64])     = o0;
            *reinterpret_cast<float4*>(&g_xr[(size_t)n * 64 + j - 64 + 4]) = o1;
        }
    }
}

// ---------------- kernel 4: edge scatter (push, f32 v4 reds) -----------------
__global__ void edge_scatter(const int* __restrict__ ei) {
    int tid = threadIdx.x;
    int e = blockIdx.x * 16 + (tid >> 4);
    int t = tid & 15;
    if (e >= N_EDGES) return;
    int src = __ldg(&ei[e]);
    int dst = __ldg(&ei[N_EDGES + e]);

    const float4* ysrc = reinterpret_cast<const float4*>(g_y + (size_t)src * 64);
    float4 v = __ldg(ysrc + t);
    float* dptr = g_agg + (size_t)dst * 64 + t * 4;
    asm volatile("red.global.add.v4.f32 [%0], {%1, %2, %3, %4};"
                 :: "l"(dptr), "f"(v.x), "f"(v.y), "f"(v.z), "f"(v.w)
                 : "memory");
    if (t == 0) {
        float* dp = g_deg + dst;
        asm volatile("red.global.add.f32 [%0], %1;" :: "l"(dp), "f"(1.0f) : "memory");
    }
}

// ---------------- kernel 5: combine + per-graph pool (4x parallelism) --------
#define POOL_BLOCKS 592
#define POOL_WARPS  (POOL_BLOCKS * 8)
#define POOL_CHUNK  ((N_NODES + POOL_WARPS - 1) / POOL_WARPS)
__global__ void combine_pool(const float* __restrict__ bl,
                             const int* __restrict__ batch) {
    int wid = (blockIdx.x * blockDim.x + threadIdx.x) >> 5;
    int lane = threadIdx.x & 31;
    int start = wid * POOL_CHUNK;
    if (start >= N_NODES) return;
    int end = min(start + POOL_CHUNK, N_NODES);

    float bl0 = bl[lane], bl1 = bl[lane + 32];
    float acc0 = 0.f, acc1 = 0.f, cnt = 0.f;
    int cur = batch[start];

    for (int n = start; n < end; n++) {
        int b = batch[n];
        if (b != cur) {
            atomicAdd(&g_gsum[cur * 64 + lane], acc0);
            atomicAdd(&g_gsum[cur * 64 + lane + 32], acc1);
            if (lane == 0) atomicAdd(&g_gcnt[cur], cnt);
            acc0 = acc1 = cnt = 0.f;
            cur = b;
        }
        float inv = 1.0f / fmaxf(g_deg[n], 1.0f);
        size_t base = (size_t)n * 64;
        float h0 = fmaxf(fmaf(g_agg[base + lane],      inv, g_xr[base + lane]      + bl0), 0.f);
        float h1 = fmaxf(fmaf(g_agg[base + lane + 32], inv, g_xr[base + lane + 32] + bl1), 0.f);
        acc0 += h0; acc1 += h1; cnt += 1.f;
    }
    atomicAdd(&g_gsum[cur * 64 + lane], acc0);
    atomicAdd(&g_gsum[cur * 64 + lane + 32], acc1);
    if (lane == 0) atomicAdd(&g_gcnt[cur], cnt);
}

// ---------------- kernel 6: final MLP (16 graphs, 1 block) -------------------
__global__ void final_mlp(const float* __restrict__ pk, const float* __restrict__ ck,
                          const float* __restrict__ Wp, const float* __restrict__ bp,
                          const float* __restrict__ Wc, const float* __restrict__ bc,
                          const float* __restrict__ Wh1, const float* __restrict__ bh1,
                          const float* __restrict__ Wh2, const float* __restrict__ bh2,
                          float* __restrict__ out) {
    __shared__ float z[NG][128];
    int w = threadIdx.x >> 5;
    int lane = threadIdx.x & 31;

    float cnt = fmaxf(g_gcnt[w], 1.0f);
    z[w][lane]      = g_gsum[w * 64 + lane] / cnt;
    z[w][lane + 32] = g_gsum[w * 64 + lane + 32] / cnt;

    float s = bp[lane];
#pragma unroll
    for (int k = 0; k < 7; k++) s = fmaf(pk[w * 7 + k], Wp[lane * 7 + k], s);
    z[w][64 + lane] = fmaxf(s, 0.f);

    s = bc[lane];
#pragma unroll
    for (int k = 0; k < 4; k++) s = fmaf(ck[w * 4 + k], Wc[lane * 4 + k], s);
    z[w][96 + lane] = fmaxf(s, 0.f);
    __syncwarp();

    float a0 = bh1[lane], a1 = bh1[lane + 32];
#pragma unroll 4
    for (int k = 0; k < 128; k++) {
        float zv = z[w][k];
        a0 = fmaf(zv, Wh1[lane * 128 + k], a0);
        a1 = fmaf(zv, Wh1[(lane + 32) * 128 + k], a1);
    }
    a0 = fmaxf(a0, 0.f);
    a1 = fmaxf(a1, 0.f);
    float r = a0 * Wh2[lane] + a1 * Wh2[lane + 32];
#pragma unroll
    for (int off = 16; off > 0; off >>= 1) r += __shfl_down_sync(0xffffffffu, r, off);
    if (lane == 0) out[w] = r + bh2[0];
}

// ---------------- launch -----------------------------------------------------
extern "C" void kernel_launch(void* const* d_in, const int* in_sizes, int n_in,
                              void* d_out, int out_size) {
    const float* x    = (const float*)d_in[0];
    const float* pk   = (const float*)d_in[1];
    const float* ck   = (const float*)d_in[2];
    const float* Wl   = (const float*)d_in[3];
    const float* bl   = (const float*)d_in[4];
    const float* Wr   = (const float*)d_in[5];
    const float* Wp   = (const float*)d_in[6];
    const float* bp   = (const float*)d_in[7];
    const float* Wc   = (const float*)d_in[8];
    const float* bc   = (const float*)d_in[9];
    const float* Wh1  = (const float*)d_in[10];
    const float* bh1  = (const float*)d_in[11];
    const float* Wh2  = (const float*)d_in[12];
    const float* bh2  = (const float*)d_in[13];
    const int*   ei   = (const int*)d_in[14];
    const int*   batch= (const int*)d_in[15];
    float* out = (float*)d_out;

    // slot 1: zero agg/deg
    zero_agg<<<2048, 256>>>();

    // slot 2: node GEMM
    int gemm_smem = (128 * 128 + GEMM_BM * 132) * (int)sizeof(float);
    cudaFuncSetAttribute(node_gemm, cudaFuncAttributeMaxDynamicSharedMemorySize, gemm_smem);
    node_gemm<<<(N_NODES + GEMM_BM - 1) / GEMM_BM, 256, gemm_smem>>>(x, Wl, Wr);

    // slot 3: tiny zero (independent of gemm; placed here so edge_scatter is slot 4)
    zero_small<<<1, 1024>>>();

    // slot 4: edge scatter  <-- lands in the profiled slot
    edge_scatter<<<(N_EDGES + 15) / 16, 256>>>(ei);

    // slot 5: combine + pool
    combine_pool<<<POOL_BLOCKS, 256>>>(bl, batch);

    // slot 6: final MLP
    final_mlp<<<1, 512>>>(pk, ck, Wp, bp, Wc, bc, Wh1, bh1, Wh2, bh2, out);

    (void)in_sizes; (void)n_in; (void)out_size;
}